// round 15
// baseline (speedup 1.0000x reference)
#include <cuda_runtime.h>
#include <cuda_fp16.h>

#define NN   100000
#define EE   1600000
#define HID  128
#define EMBD 64
#define KC   100
#define NB   98          // ceil(100000/1024) scan blocks

// ---------------- scratch -----------------------------------------------------
__device__ float  g_dis[NN];
__device__ __half g_Hh[NN * HID];      // x @ W1, fp16 storage
__device__ float  g_H1[NN * HID];      // gathered h1 (fp32)
__device__ __half g_H2h[NN * EMBD];    // relu(bn(h1)) @ W2, fp16 storage
__device__ float  g_sum[HID];
__device__ float  g_sumsq[HID];
__device__ float  g_scale[HID];
__device__ float  g_shift[HID];
__device__ int    g_cnt[NN];
__device__ int    g_fill[NN];
__device__ int    g_rowstart[NN + 1];
__device__ int    g_blocksum[NB];
__device__ int    g_blockoff[NB];
__device__ int    g_esrc[EE];
__device__ float  g_enorm[EE];

struct alignas(16) H8 { __half2 a, b, c, d; };

// ---------------- init / degree / scan / fill --------------------------------
__global__ void k_init() {
    int i = blockIdx.x * blockDim.x + threadIdx.x;
    if (i < NN)  { g_cnt[i] = 0; g_fill[i] = 0; }
    if (i < HID) { g_sum[i] = 0.f; g_sumsq[i] = 0.f; }
}

__global__ void k_count(const int* __restrict__ ei) {
    int e = blockIdx.x * blockDim.x + threadIdx.x;
    if (e < EE) {
        int dst = ei[EE + e];
        if ((unsigned)dst < NN) atomicAdd(&g_cnt[dst], 1);
    }
}

__global__ void k_scan1() {
    __shared__ int s[1024];
    int t = threadIdx.x;
    int i = blockIdx.x * 1024 + t;
    int v = (i < NN) ? g_cnt[i] : 0;
    s[t] = v;
    __syncthreads();
#pragma unroll
    for (int off = 1; off < 1024; off <<= 1) {
        int add = (t >= off) ? s[t - off] : 0;
        __syncthreads();
        s[t] += add;
        __syncthreads();
    }
    if (i < NN) g_rowstart[i] = s[t] - v;
    if (t == 1023) g_blocksum[blockIdx.x] = s[1023];
}

__global__ void k_scan2() {
    __shared__ int s[128];
    int t = threadIdx.x;
    int v = (t < NB) ? g_blocksum[t] : 0;
    s[t] = v;
    __syncthreads();
#pragma unroll
    for (int off = 1; off < 128; off <<= 1) {
        int add = (t >= off) ? s[t - off] : 0;
        __syncthreads();
        s[t] += add;
        __syncthreads();
    }
    if (t < NB) g_blockoff[t] = s[t] - v;
}

__global__ void k_scan3() {
    int i = blockIdx.x * blockDim.x + threadIdx.x;
    if (i < NN) {
        g_rowstart[i] += g_blockoff[i >> 10];
        g_dis[i] = rsqrtf((float)(g_cnt[i] + 1));   // fused deg^-1/2
    }
    if (i == 0) g_rowstart[NN] = EE;
}

__global__ void k_fill(const int* __restrict__ ei) {
    int e = blockIdx.x * blockDim.x + threadIdx.x;
    if (e >= EE) return;
    int src = ei[e];
    int dst = ei[EE + e];
    if ((unsigned)src >= NN || (unsigned)dst >= NN) return;
    int pos = g_rowstart[dst] + atomicAdd(&g_fill[dst], 1);
    g_esrc[pos]  = src;
    g_enorm[pos] = g_dis[src] * g_dis[dst];
}

// ---------------- GEMM1: H = x @ W1 -> fp16 (BM=128,BN=128,BK=16,8x8) --------
__global__ void __launch_bounds__(256) k_gemm1(const float* __restrict__ x,
                                               const float* __restrict__ W) {
    __shared__ float Xs[16 * 132];
    __shared__ float Ws[16 * 128];
    int tid  = threadIdx.x;
    int row0 = blockIdx.x * 128;
    int ty = tid >> 4, tx = tid & 15;
    int r0 = ty * 8, c0 = tx * 8;

    int lrow  = tid >> 1;
    int lhalf = (tid & 1) * 8;
    int wk = tid >> 4;
    int wn = (tid & 15) * 8;

    float acc[8][8];
#pragma unroll
    for (int i = 0; i < 8; i++)
#pragma unroll
        for (int j = 0; j < 8; j++) acc[i][j] = 0.f;

    for (int kk = 0; kk < 128; kk += 16) {
        int gr = row0 + lrow;
        float4 xa = {0,0,0,0}, xb = {0,0,0,0};
        if (gr < NN) {
            xa = *(const float4*)&x[gr * 128 + kk + lhalf];
            xb = *(const float4*)&x[gr * 128 + kk + lhalf + 4];
        }
        Xs[(lhalf + 0) * 132 + lrow] = xa.x;
        Xs[(lhalf + 1) * 132 + lrow] = xa.y;
        Xs[(lhalf + 2) * 132 + lrow] = xa.z;
        Xs[(lhalf + 3) * 132 + lrow] = xa.w;
        Xs[(lhalf + 4) * 132 + lrow] = xb.x;
        Xs[(lhalf + 5) * 132 + lrow] = xb.y;
        Xs[(lhalf + 6) * 132 + lrow] = xb.z;
        Xs[(lhalf + 7) * 132 + lrow] = xb.w;
        *(float4*)&Ws[wk * 128 + wn]     = *(const float4*)&W[(kk + wk) * 128 + wn];
        *(float4*)&Ws[wk * 128 + wn + 4] = *(const float4*)&W[(kk + wk) * 128 + wn + 4];
        __syncthreads();
#pragma unroll
        for (int k = 0; k < 16; k++) {
            float4 a0 = *(const float4*)&Xs[k * 132 + r0];
            float4 a1 = *(const float4*)&Xs[k * 132 + r0 + 4];
            float4 b0 = *(const float4*)&Ws[k * 128 + c0];
            float4 b1 = *(const float4*)&Ws[k * 128 + c0 + 4];
            float av[8] = {a0.x, a0.y, a0.z, a0.w, a1.x, a1.y, a1.z, a1.w};
            float bv[8] = {b0.x, b0.y, b0.z, b0.w, b1.x, b1.y, b1.z, b1.w};
#pragma unroll
            for (int i = 0; i < 8; i++)
#pragma unroll
                for (int j = 0; j < 8; j++)
                    acc[i][j] = fmaf(av[i], bv[j], acc[i][j]);
        }
        __syncthreads();
    }
#pragma unroll
    for (int i = 0; i < 8; i++) {
        int gr = row0 + r0 + i;
        if (gr < NN) {
            H8 v;
            v.a = __floats2half2_rn(acc[i][0], acc[i][1]);
            v.b = __floats2half2_rn(acc[i][2], acc[i][3]);
            v.c = __floats2half2_rn(acc[i][4], acc[i][5]);
            v.d = __floats2half2_rn(acc[i][6], acc[i][7]);
            *(H8*)&g_Hh[gr * 128 + c0] = v;
        }
    }
}

// ---------------- gather 1: warp/node, fp16 rows (8B per lane) ---------------
__device__ __forceinline__ void h4_fma(float4& acc, const __half* p, float n) {
    uint2 raw = *(const uint2*)p;
    float2 f0 = __half22float2(*(const __half2*)&raw.x);
    float2 f1 = __half22float2(*(const __half2*)&raw.y);
    acc.x = fmaf(f0.x, n, acc.x); acc.y = fmaf(f0.y, n, acc.y);
    acc.z = fmaf(f1.x, n, acc.z); acc.w = fmaf(f1.y, n, acc.w);
}

__global__ void k_gather1(const float* __restrict__ b1) {
    int w    = (blockIdx.x * blockDim.x + threadIdx.x) >> 5;
    int lane = threadIdx.x & 31;
    if (w >= NN) return;
    int beg = g_rowstart[w], end = g_rowstart[w + 1];
    float4 acc = {0.f, 0.f, 0.f, 0.f};
    int p = beg;
    for (; p + 4 <= end; p += 4) {
        int   s0 = __ldg(&g_esrc[p]),     s1 = __ldg(&g_esrc[p + 1]);
        int   s2 = __ldg(&g_esrc[p + 2]), s3 = __ldg(&g_esrc[p + 3]);
        float n0 = __ldg(&g_enorm[p]),     n1 = __ldg(&g_enorm[p + 1]);
        float n2 = __ldg(&g_enorm[p + 2]), n3 = __ldg(&g_enorm[p + 3]);
        h4_fma(acc, &g_Hh[s0 * HID + lane * 4], n0);
        h4_fma(acc, &g_Hh[s1 * HID + lane * 4], n1);
        h4_fma(acc, &g_Hh[s2 * HID + lane * 4], n2);
        h4_fma(acc, &g_Hh[s3 * HID + lane * 4], n3);
    }
    for (; p < end; p++) {
        int   s0 = __ldg(&g_esrc[p]);
        float n0 = __ldg(&g_enorm[p]);
        h4_fma(acc, &g_Hh[s0 * HID + lane * 4], n0);
    }
    float dn = g_dis[w];
    float sl = dn * dn;
    h4_fma(acc, &g_Hh[w * HID + lane * 4], sl);
    float4 bb = *(const float4*)&b1[lane * 4];
    acc.x += bb.x; acc.y += bb.y; acc.z += bb.z; acc.w += bb.w;
    *(float4*)&g_H1[w * HID + lane * 4] = acc;
}

// ---------------- BN stats ----------------------------------------------------
__global__ void k_bnstats() {
    int c = threadIdx.x;
    float s = 0.f, s2 = 0.f;
    for (int r = blockIdx.x; r < NN; r += gridDim.x) {
        float v = g_H1[r * HID + c];
        s += v; s2 += v * v;
    }
    atomicAdd(&g_sum[c], s);
    atomicAdd(&g_sumsq[c], s2);
}

__global__ void k_bn_final(const float* __restrict__ gamma, const float* __restrict__ beta) {
    int c = threadIdx.x;
    float mu   = g_sum[c]   * (1.0f / NN);
    float var  = g_sumsq[c] * (1.0f / NN) - mu * mu;
    float istd = rsqrtf(var + 1e-5f);
    float sc   = istd * gamma[c];
    g_scale[c] = sc;
    g_shift[c] = beta[c] - mu * sc;
}

// ---------------- GEMM2 fused BN+ReLU -> fp16 (BM=128,BN=64,BK=16,4x8) -------
__global__ void __launch_bounds__(256) k_gemm2(const float* __restrict__ W2) {
    __shared__ float Xs[16 * 132];
    __shared__ float Ws[16 * 64];
    __shared__ float Ss[128], Hs[128];
    int tid  = threadIdx.x;
    int row0 = blockIdx.x * 128;
    int ty = tid >> 3, tx = tid & 7;
    int r0 = ty * 4, c0 = tx * 8;

    if (tid < 128) { Ss[tid] = g_scale[tid]; Hs[tid] = g_shift[tid]; }

    int lrow  = tid >> 1;
    int lhalf = (tid & 1) * 8;
    int wk = tid >> 4;
    int wn = (tid & 15) * 4;

    float acc[4][8];
#pragma unroll
    for (int i = 0; i < 4; i++)
#pragma unroll
        for (int j = 0; j < 8; j++) acc[i][j] = 0.f;

    __syncthreads();
    for (int kk = 0; kk < 128; kk += 16) {
        int gr = row0 + lrow;
        float v[8] = {0,0,0,0,0,0,0,0};
        if (gr < NN) {
            float4 xa = *(const float4*)&g_H1[gr * 128 + kk + lhalf];
            float4 xb = *(const float4*)&g_H1[gr * 128 + kk + lhalf + 4];
            float xv[8] = {xa.x, xa.y, xa.z, xa.w, xb.x, xb.y, xb.z, xb.w};
#pragma unroll
            for (int j = 0; j < 8; j++) {
                int cc = kk + lhalf + j;
                v[j] = fmaxf(fmaf(xv[j], Ss[cc], Hs[cc]), 0.f);
            }
        }
#pragma unroll
        for (int j = 0; j < 8; j++)
            Xs[(lhalf + j) * 132 + lrow] = v[j];
        *(float4*)&Ws[wk * 64 + wn] = *(const float4*)&W2[(kk + wk) * 64 + wn];
        __syncthreads();
#pragma unroll
        for (int k = 0; k < 16; k++) {
            float4 a0 = *(const float4*)&Xs[k * 132 + r0];
            float4 b0 = *(const float4*)&Ws[k * 64 + c0];
            float4 b1 = *(const float4*)&Ws[k * 64 + c0 + 4];
            float av[4] = {a0.x, a0.y, a0.z, a0.w};
            float bv[8] = {b0.x, b0.y, b0.z, b0.w, b1.x, b1.y, b1.z, b1.w};
#pragma unroll
            for (int i = 0; i < 4; i++)
#pragma unroll
                for (int j = 0; j < 8; j++)
                    acc[i][j] = fmaf(av[i], bv[j], acc[i][j]);
        }
        __syncthreads();
    }
#pragma unroll
    for (int i = 0; i < 4; i++) {
        int gr = row0 + r0 + i;
        if (gr < NN) {
            H8 v;
            v.a = __floats2half2_rn(acc[i][0], acc[i][1]);
            v.b = __floats2half2_rn(acc[i][2], acc[i][3]);
            v.c = __floats2half2_rn(acc[i][4], acc[i][5]);
            v.d = __floats2half2_rn(acc[i][6], acc[i][7]);
            *(H8*)&g_H2h[gr * 64 + c0] = v;
        }
    }
}

// ---------------- gather 2: warp/node, fp16 rows (4B per lane) ---------------
__global__ void k_gather2(const float* __restrict__ b2, float* __restrict__ out) {
    int w    = (blockIdx.x * blockDim.x + threadIdx.x) >> 5;
    int lane = threadIdx.x & 31;
    if (w >= NN) return;
    int beg = g_rowstart[w], end = g_rowstart[w + 1];
    float2 acc = {0.f, 0.f};
    int p = beg;
    for (; p + 4 <= end; p += 4) {
        int   s0 = __ldg(&g_esrc[p]),     s1 = __ldg(&g_esrc[p + 1]);
        int   s2 = __ldg(&g_esrc[p + 2]), s3 = __ldg(&g_esrc[p + 3]);
        float n0 = __ldg(&g_enorm[p]),     n1 = __ldg(&g_enorm[p + 1]);
        float n2 = __ldg(&g_enorm[p + 2]), n3 = __ldg(&g_enorm[p + 3]);
        float2 v0 = __half22float2(*(const __half2*)&g_H2h[s0 * EMBD + lane * 2]);
        float2 v1 = __half22float2(*(const __half2*)&g_H2h[s1 * EMBD + lane * 2]);
        float2 v2 = __half22float2(*(const __half2*)&g_H2h[s2 * EMBD + lane * 2]);
        float2 v3 = __half22float2(*(const __half2*)&g_H2h[s3 * EMBD + lane * 2]);
        acc.x = fmaf(v0.x, n0, acc.x); acc.y = fmaf(v0.y, n0, acc.y);
        acc.x = fmaf(v1.x, n1, acc.x); acc.y = fmaf(v1.y, n1, acc.y);
        acc.x = fmaf(v2.x, n2, acc.x); acc.y = fmaf(v2.y, n2, acc.y);
        acc.x = fmaf(v3.x, n3, acc.x); acc.y = fmaf(v3.y, n3, acc.y);
    }
    for (; p < end; p++) {
        int   s0 = __ldg(&g_esrc[p]);
        float n0 = __ldg(&g_enorm[p]);
        float2 v0 = __half22float2(*(const __half2*)&g_H2h[s0 * EMBD + lane * 2]);
        acc.x = fmaf(v0.x, n0, acc.x); acc.y = fmaf(v0.y, n0, acc.y);
    }
    float dn = g_dis[w];
    float sl = dn * dn;
    float2 h  = __half22float2(*(const __half2*)&g_H2h[w * EMBD + lane * 2]);
    float2 bb = *(const float2*)&b2[lane * 2];
    acc.x += sl * h.x + bb.x;
    acc.y += sl * h.y + bb.y;
    *(float2*)&out[w * EMBD + lane * 2] = acc;
}

// ---------------- warp-per-node fused logits + softmax -----------------------
// lane q-th logit: k = lane + 32q. Centers transposed in smem: CsT[j][k].
__global__ void __launch_bounds__(256) k_logits(const float* __restrict__ centers,
                                                const float* __restrict__ temp,
                                                float* __restrict__ out) {
    __shared__ float CsT[EMBD * KC];      // [j][k], 25.6 KB
    int tid = threadIdx.x;
    for (int i = tid; i < KC * EMBD; i += 256) {
        int k = i / EMBD, j = i % EMBD;   // centers[k][j]
        CsT[j * KC + k] = centers[i];
    }
    __syncthreads();

    int w    = (blockIdx.x * 256 + tid) >> 5;
    int lane = tid & 31;
    if (w >= NN) return;

    // broadcast-load emb row into registers (same addrs across warp -> 1 wavefront)
    float e[EMBD];
    const float4* e4 = (const float4*)&out[w * EMBD];
#pragma unroll
    for (int i = 0; i < 16; i++) {
        float4 r = e4[i];
        e[4 * i + 0] = r.x; e[4 * i + 1] = r.y; e[4 * i + 2] = r.z; e[4 * i + 3] = r.w;
    }

    float inv_t = 1.0f / temp[0];
    float lg[4];
    float m = -1e30f;
#pragma unroll
    for (int q = 0; q < 4; q++) {
        int k = lane + 32 * q;
        float d = -1e30f;
        if (k < KC) {
            float d0 = 0.f, d1 = 0.f, d2 = 0.f, d3 = 0.f;
#pragma unroll
            for (int j = 0; j < EMBD; j += 4) {
                d0 = fmaf(e[j + 0], CsT[(j + 0) * KC + k], d0);
                d1 = fmaf(e[j + 1], CsT[(j + 1) * KC + k], d1);
                d2 = fmaf(e[j + 2], CsT[(j + 2) * KC + k], d2);
                d3 = fmaf(e[j + 3], CsT[(j + 3) * KC + k], d3);
            }
            d = ((d0 + d1) + (d2 + d3)) * inv_t;
            m = fmaxf(m, d);
        }
        lg[q] = d;
    }
#pragma unroll
    for (int o = 16; o > 0; o >>= 1) m = fmaxf(m, __shfl_xor_sync(0xFFFFFFFFu, m, o));
    float s = 0.f;
#pragma unroll
    for (int q = 0; q < 4; q++) {
        int k = lane + 32 * q;
        if (k < KC) { lg[q] = __expf(lg[q] - m); s += lg[q]; }
    }
#pragma unroll
    for (int o = 16; o > 0; o >>= 1) s += __shfl_xor_sync(0xFFFFFFFFu, s, o);
    float inv_s = 1.0f / s;
    float* so = out + (size_t)NN * EMBD + (size_t)w * KC;
#pragma unroll
    for (int q = 0; q < 4; q++) {
        int k = lane + 32 * q;
        if (k < KC) so[k] = lg[q] * inv_s;
    }
}

// -----------------------------------------------------------------------------
extern "C" void kernel_launch(void* const* d_in, const int* in_sizes, int n_in,
                              void* d_out, int out_size) {
    const float* x       = (const float*)d_in[0];
    const int*   ei      = (const int*)d_in[1];
    const float* W1      = (const float*)d_in[2];
    const float* b1      = (const float*)d_in[3];
    const float* gamma   = (const float*)d_in[4];
    const float* beta    = (const float*)d_in[5];
    const float* W2      = (const float*)d_in[6];
    const float* b2      = (const float*)d_in[7];
    const float* centers = (const float*)d_in[8];
    const float* temp    = (const float*)d_in[9];
    float* out = (float*)d_out;

    k_init<<<(NN + 255) / 256, 256>>>();
    k_count<<<(EE + 255) / 256, 256>>>(ei);
    k_scan1<<<NB, 1024>>>();
    k_scan2<<<1, 128>>>();
    k_scan3<<<(NN + 255) / 256, 256>>>();
    k_fill<<<(EE + 255) / 256, 256>>>(ei);
    k_gemm1<<<(NN + 127) / 128, 256>>>(x, W1);
    k_gather1<<<(NN * 32 + 255) / 256, 256>>>(b1);
    k_bnstats<<<1024, 128>>>();
    k_bn_final<<<1, 128>>>(gamma, beta);
    k_gemm2<<<(NN + 127) / 128, 256>>>(W2);
    k_gather2<<<(NN * 32 + 255) / 256, 256>>>(b2, out);
    k_logits<<<(NN * 32 + 255) / 256, 256>>>(centers, temp, out);
}

// round 16
// speedup vs baseline: 1.0765x; 1.0765x over previous
#include <cuda_runtime.h>
#include <cuda_fp16.h>

#define NN   100000
#define EE   1600000
#define HID  128
#define EMBD 64
#define KC   100
#define NB   98          // ceil(100000/1024) scan blocks
#define LBLK 400         // k_logits blocks (CsT fill amortized across ~32 nodes/warp)

// ---------------- scratch -----------------------------------------------------
__device__ float  g_dis[NN];
__device__ __half g_Hh[NN * HID];      // x @ W1, fp16 storage
__device__ float  g_H1[NN * HID];      // gathered h1 (fp32)
__device__ __half g_H2h[NN * EMBD];    // relu(bn(h1)) @ W2, fp16 storage
__device__ float  g_sum[HID];
__device__ float  g_sumsq[HID];
__device__ float  g_scale[HID];
__device__ float  g_shift[HID];
__device__ int    g_cnt[NN];
__device__ int    g_fill[NN];
__device__ int    g_rowstart[NN + 1];
__device__ int    g_blocksum[NB];
__device__ int    g_blockoff[NB];
__device__ int    g_esrc[EE];
__device__ float  g_enorm[EE];

struct alignas(16) H8 { __half2 a, b, c, d; };

// ---------------- init / degree / scan / fill --------------------------------
__global__ void k_init() {
    int i = blockIdx.x * blockDim.x + threadIdx.x;
    if (i < NN)  { g_cnt[i] = 0; g_fill[i] = 0; }
    if (i < HID) { g_sum[i] = 0.f; g_sumsq[i] = 0.f; }
}

__global__ void k_count(const int* __restrict__ ei) {
    int e = blockIdx.x * blockDim.x + threadIdx.x;
    if (e < EE) {
        int dst = ei[EE + e];
        if ((unsigned)dst < NN) atomicAdd(&g_cnt[dst], 1);
    }
}

__global__ void k_scan1() {
    __shared__ int s[1024];
    int t = threadIdx.x;
    int i = blockIdx.x * 1024 + t;
    int v = (i < NN) ? g_cnt[i] : 0;
    s[t] = v;
    __syncthreads();
#pragma unroll
    for (int off = 1; off < 1024; off <<= 1) {
        int add = (t >= off) ? s[t - off] : 0;
        __syncthreads();
        s[t] += add;
        __syncthreads();
    }
    if (i < NN) g_rowstart[i] = s[t] - v;
    if (t == 1023) g_blocksum[blockIdx.x] = s[1023];
}

__global__ void k_scan2() {
    __shared__ int s[128];
    int t = threadIdx.x;
    int v = (t < NB) ? g_blocksum[t] : 0;
    s[t] = v;
    __syncthreads();
#pragma unroll
    for (int off = 1; off < 128; off <<= 1) {
        int add = (t >= off) ? s[t - off] : 0;
        __syncthreads();
        s[t] += add;
        __syncthreads();
    }
    if (t < NB) g_blockoff[t] = s[t] - v;
}

__global__ void k_scan3() {
    int i = blockIdx.x * blockDim.x + threadIdx.x;
    if (i < NN) {
        g_rowstart[i] += g_blockoff[i >> 10];
        g_dis[i] = rsqrtf((float)(g_cnt[i] + 1));   // fused deg^-1/2
    }
    if (i == 0) g_rowstart[NN] = EE;
}

__global__ void k_fill(const int* __restrict__ ei) {
    int e = blockIdx.x * blockDim.x + threadIdx.x;
    if (e >= EE) return;
    int src = ei[e];
    int dst = ei[EE + e];
    if ((unsigned)src >= NN || (unsigned)dst >= NN) return;
    int pos = g_rowstart[dst] + atomicAdd(&g_fill[dst], 1);
    g_esrc[pos]  = src;
    g_enorm[pos] = g_dis[src] * g_dis[dst];
}

// ---------------- GEMM1: H = x @ W1 -> fp16 (BM=128,BN=128,BK=16,8x8) --------
__global__ void __launch_bounds__(256) k_gemm1(const float* __restrict__ x,
                                               const float* __restrict__ W) {
    __shared__ float Xs[16 * 132];
    __shared__ float Ws[16 * 128];
    int tid  = threadIdx.x;
    int row0 = blockIdx.x * 128;
    int ty = tid >> 4, tx = tid & 15;
    int r0 = ty * 8, c0 = tx * 8;

    int lrow  = tid >> 1;
    int lhalf = (tid & 1) * 8;
    int wk = tid >> 4;
    int wn = (tid & 15) * 8;

    float acc[8][8];
#pragma unroll
    for (int i = 0; i < 8; i++)
#pragma unroll
        for (int j = 0; j < 8; j++) acc[i][j] = 0.f;

    for (int kk = 0; kk < 128; kk += 16) {
        int gr = row0 + lrow;
        float4 xa = {0,0,0,0}, xb = {0,0,0,0};
        if (gr < NN) {
            xa = *(const float4*)&x[gr * 128 + kk + lhalf];
            xb = *(const float4*)&x[gr * 128 + kk + lhalf + 4];
        }
        Xs[(lhalf + 0) * 132 + lrow] = xa.x;
        Xs[(lhalf + 1) * 132 + lrow] = xa.y;
        Xs[(lhalf + 2) * 132 + lrow] = xa.z;
        Xs[(lhalf + 3) * 132 + lrow] = xa.w;
        Xs[(lhalf + 4) * 132 + lrow] = xb.x;
        Xs[(lhalf + 5) * 132 + lrow] = xb.y;
        Xs[(lhalf + 6) * 132 + lrow] = xb.z;
        Xs[(lhalf + 7) * 132 + lrow] = xb.w;
        *(float4*)&Ws[wk * 128 + wn]     = *(const float4*)&W[(kk + wk) * 128 + wn];
        *(float4*)&Ws[wk * 128 + wn + 4] = *(const float4*)&W[(kk + wk) * 128 + wn + 4];
        __syncthreads();
#pragma unroll
        for (int k = 0; k < 16; k++) {
            float4 a0 = *(const float4*)&Xs[k * 132 + r0];
            float4 a1 = *(const float4*)&Xs[k * 132 + r0 + 4];
            float4 b0 = *(const float4*)&Ws[k * 128 + c0];
            float4 b1 = *(const float4*)&Ws[k * 128 + c0 + 4];
            float av[8] = {a0.x, a0.y, a0.z, a0.w, a1.x, a1.y, a1.z, a1.w};
            float bv[8] = {b0.x, b0.y, b0.z, b0.w, b1.x, b1.y, b1.z, b1.w};
#pragma unroll
            for (int i = 0; i < 8; i++)
#pragma unroll
                for (int j = 0; j < 8; j++)
                    acc[i][j] = fmaf(av[i], bv[j], acc[i][j]);
        }
        __syncthreads();
    }
#pragma unroll
    for (int i = 0; i < 8; i++) {
        int gr = row0 + r0 + i;
        if (gr < NN) {
            H8 v;
            v.a = __floats2half2_rn(acc[i][0], acc[i][1]);
            v.b = __floats2half2_rn(acc[i][2], acc[i][3]);
            v.c = __floats2half2_rn(acc[i][4], acc[i][5]);
            v.d = __floats2half2_rn(acc[i][6], acc[i][7]);
            *(H8*)&g_Hh[gr * 128 + c0] = v;
        }
    }
}

// ---------------- gather 1: warp/node, fp16 rows (8B per lane) ---------------
__device__ __forceinline__ void h4_fma(float4& acc, const __half* p, float n) {
    uint2 raw = *(const uint2*)p;
    float2 f0 = __half22float2(*(const __half2*)&raw.x);
    float2 f1 = __half22float2(*(const __half2*)&raw.y);
    acc.x = fmaf(f0.x, n, acc.x); acc.y = fmaf(f0.y, n, acc.y);
    acc.z = fmaf(f1.x, n, acc.z); acc.w = fmaf(f1.y, n, acc.w);
}

__global__ void k_gather1(const float* __restrict__ b1) {
    int w    = (blockIdx.x * blockDim.x + threadIdx.x) >> 5;
    int lane = threadIdx.x & 31;
    if (w >= NN) return;
    int beg = g_rowstart[w], end = g_rowstart[w + 1];
    float4 acc = {0.f, 0.f, 0.f, 0.f};
    int p = beg;
    for (; p + 4 <= end; p += 4) {
        int   s0 = __ldg(&g_esrc[p]),     s1 = __ldg(&g_esrc[p + 1]);
        int   s2 = __ldg(&g_esrc[p + 2]), s3 = __ldg(&g_esrc[p + 3]);
        float n0 = __ldg(&g_enorm[p]),     n1 = __ldg(&g_enorm[p + 1]);
        float n2 = __ldg(&g_enorm[p + 2]), n3 = __ldg(&g_enorm[p + 3]);
        h4_fma(acc, &g_Hh[s0 * HID + lane * 4], n0);
        h4_fma(acc, &g_Hh[s1 * HID + lane * 4], n1);
        h4_fma(acc, &g_Hh[s2 * HID + lane * 4], n2);
        h4_fma(acc, &g_Hh[s3 * HID + lane * 4], n3);
    }
    for (; p < end; p++) {
        int   s0 = __ldg(&g_esrc[p]);
        float n0 = __ldg(&g_enorm[p]);
        h4_fma(acc, &g_Hh[s0 * HID + lane * 4], n0);
    }
    float dn = g_dis[w];
    float sl = dn * dn;
    h4_fma(acc, &g_Hh[w * HID + lane * 4], sl);
    float4 bb = *(const float4*)&b1[lane * 4];
    acc.x += bb.x; acc.y += bb.y; acc.z += bb.z; acc.w += bb.w;
    *(float4*)&g_H1[w * HID + lane * 4] = acc;
}

// ---------------- BN stats ----------------------------------------------------
__global__ void k_bnstats() {
    int c = threadIdx.x;
    float s = 0.f, s2 = 0.f;
    for (int r = blockIdx.x; r < NN; r += gridDim.x) {
        float v = g_H1[r * HID + c];
        s += v; s2 += v * v;
    }
    atomicAdd(&g_sum[c], s);
    atomicAdd(&g_sumsq[c], s2);
}

__global__ void k_bn_final(const float* __restrict__ gamma, const float* __restrict__ beta) {
    int c = threadIdx.x;
    float mu   = g_sum[c]   * (1.0f / NN);
    float var  = g_sumsq[c] * (1.0f / NN) - mu * mu;
    float istd = rsqrtf(var + 1e-5f);
    float sc   = istd * gamma[c];
    g_scale[c] = sc;
    g_shift[c] = beta[c] - mu * sc;
}

// ---------------- GEMM2 fused BN+ReLU -> fp16 (BM=128,BN=64,BK=16,4x8) -------
__global__ void __launch_bounds__(256) k_gemm2(const float* __restrict__ W2) {
    __shared__ float Xs[16 * 132];
    __shared__ float Ws[16 * 64];
    __shared__ float Ss[128], Hs[128];
    int tid  = threadIdx.x;
    int row0 = blockIdx.x * 128;
    int ty = tid >> 3, tx = tid & 7;
    int r0 = ty * 4, c0 = tx * 8;

    if (tid < 128) { Ss[tid] = g_scale[tid]; Hs[tid] = g_shift[tid]; }

    int lrow  = tid >> 1;
    int lhalf = (tid & 1) * 8;
    int wk = tid >> 4;
    int wn = (tid & 15) * 4;

    float acc[4][8];
#pragma unroll
    for (int i = 0; i < 4; i++)
#pragma unroll
        for (int j = 0; j < 8; j++) acc[i][j] = 0.f;

    __syncthreads();
    for (int kk = 0; kk < 128; kk += 16) {
        int gr = row0 + lrow;
        float v[8] = {0,0,0,0,0,0,0,0};
        if (gr < NN) {
            float4 xa = *(const float4*)&g_H1[gr * 128 + kk + lhalf];
            float4 xb = *(const float4*)&g_H1[gr * 128 + kk + lhalf + 4];
            float xv[8] = {xa.x, xa.y, xa.z, xa.w, xb.x, xb.y, xb.z, xb.w};
#pragma unroll
            for (int j = 0; j < 8; j++) {
                int cc = kk + lhalf + j;
                v[j] = fmaxf(fmaf(xv[j], Ss[cc], Hs[cc]), 0.f);
            }
        }
#pragma unroll
        for (int j = 0; j < 8; j++)
            Xs[(lhalf + j) * 132 + lrow] = v[j];
        *(float4*)&Ws[wk * 64 + wn] = *(const float4*)&W2[(kk + wk) * 64 + wn];
        __syncthreads();
#pragma unroll
        for (int k = 0; k < 16; k++) {
            float4 a0 = *(const float4*)&Xs[k * 132 + r0];
            float4 b0 = *(const float4*)&Ws[k * 64 + c0];
            float4 b1 = *(const float4*)&Ws[k * 64 + c0 + 4];
            float av[4] = {a0.x, a0.y, a0.z, a0.w};
            float bv[8] = {b0.x, b0.y, b0.z, b0.w, b1.x, b1.y, b1.z, b1.w};
#pragma unroll
            for (int i = 0; i < 4; i++)
#pragma unroll
                for (int j = 0; j < 8; j++)
                    acc[i][j] = fmaf(av[i], bv[j], acc[i][j]);
        }
        __syncthreads();
    }
#pragma unroll
    for (int i = 0; i < 4; i++) {
        int gr = row0 + r0 + i;
        if (gr < NN) {
            H8 v;
            v.a = __floats2half2_rn(acc[i][0], acc[i][1]);
            v.b = __floats2half2_rn(acc[i][2], acc[i][3]);
            v.c = __floats2half2_rn(acc[i][4], acc[i][5]);
            v.d = __floats2half2_rn(acc[i][6], acc[i][7]);
            *(H8*)&g_H2h[gr * 64 + c0] = v;
        }
    }
}

// ---------------- gather 2: warp/node, fp16 rows (4B per lane) ---------------
__global__ void k_gather2(const float* __restrict__ b2, float* __restrict__ out) {
    int w    = (blockIdx.x * blockDim.x + threadIdx.x) >> 5;
    int lane = threadIdx.x & 31;
    if (w >= NN) return;
    int beg = g_rowstart[w], end = g_rowstart[w + 1];
    float2 acc = {0.f, 0.f};
    int p = beg;
    for (; p + 4 <= end; p += 4) {
        int   s0 = __ldg(&g_esrc[p]),     s1 = __ldg(&g_esrc[p + 1]);
        int   s2 = __ldg(&g_esrc[p + 2]), s3 = __ldg(&g_esrc[p + 3]);
        float n0 = __ldg(&g_enorm[p]),     n1 = __ldg(&g_enorm[p + 1]);
        float n2 = __ldg(&g_enorm[p + 2]), n3 = __ldg(&g_enorm[p + 3]);
        float2 v0 = __half22float2(*(const __half2*)&g_H2h[s0 * EMBD + lane * 2]);
        float2 v1 = __half22float2(*(const __half2*)&g_H2h[s1 * EMBD + lane * 2]);
        float2 v2 = __half22float2(*(const __half2*)&g_H2h[s2 * EMBD + lane * 2]);
        float2 v3 = __half22float2(*(const __half2*)&g_H2h[s3 * EMBD + lane * 2]);
        acc.x = fmaf(v0.x, n0, acc.x); acc.y = fmaf(v0.y, n0, acc.y);
        acc.x = fmaf(v1.x, n1, acc.x); acc.y = fmaf(v1.y, n1, acc.y);
        acc.x = fmaf(v2.x, n2, acc.x); acc.y = fmaf(v2.y, n2, acc.y);
        acc.x = fmaf(v3.x, n3, acc.x); acc.y = fmaf(v3.y, n3, acc.y);
    }
    for (; p < end; p++) {
        int   s0 = __ldg(&g_esrc[p]);
        float n0 = __ldg(&g_enorm[p]);
        float2 v0 = __half22float2(*(const __half2*)&g_H2h[s0 * EMBD + lane * 2]);
        acc.x = fmaf(v0.x, n0, acc.x); acc.y = fmaf(v0.y, n0, acc.y);
    }
    float dn = g_dis[w];
    float sl = dn * dn;
    float2 h  = __half22float2(*(const __half2*)&g_H2h[w * EMBD + lane * 2]);
    float2 bb = *(const float2*)&b2[lane * 2];
    acc.x += sl * h.x + bb.x;
    acc.y += sl * h.y + bb.y;
    *(float2*)&out[w * EMBD + lane * 2] = acc;
}

// ---------------- warp-per-node fused logits + softmax (grid-stride) ---------
// Fixed LBLK blocks; CsT filled once per block, reused by each warp across
// ~NN/(LBLK*8) nodes. lane q-th logit: k = lane + 32q; CsT transposed [j][k].
__global__ void __launch_bounds__(256) k_logits(const float* __restrict__ centers,
                                                const float* __restrict__ temp,
                                                float* __restrict__ out) {
    __shared__ float CsT[EMBD * KC];      // [j][k], 25.6 KB
    int tid = threadIdx.x;
    for (int i = tid; i < KC * EMBD; i += 256) {
        int k = i >> 6, j = i & 63;       // centers[k][j], EMBD=64
        CsT[j * KC + k] = centers[i];
    }
    __syncthreads();

    int lane    = tid & 31;
    int warp0   = blockIdx.x * 8 + (tid >> 5);
    int nwarps  = LBLK * 8;
    float inv_t = 1.0f / temp[0];

    for (int w = warp0; w < NN; w += nwarps) {
        // broadcast-load emb row (same addrs across warp -> 1 wavefront each)
        float e[EMBD];
        const float4* e4 = (const float4*)&out[w * EMBD];
#pragma unroll
        for (int i = 0; i < 16; i++) {
            float4 r = e4[i];
            e[4 * i + 0] = r.x; e[4 * i + 1] = r.y; e[4 * i + 2] = r.z; e[4 * i + 3] = r.w;
        }

        float lg[4];
        float m = -1e30f;
#pragma unroll
        for (int q = 0; q < 4; q++) {
            int k = lane + 32 * q;
            float d = -1e30f;
            if (k < KC) {
                float d0 = 0.f, d1 = 0.f, d2 = 0.f, d3 = 0.f;
#pragma unroll
                for (int j = 0; j < EMBD; j += 4) {
                    d0 = fmaf(e[j + 0], CsT[(j + 0) * KC + k], d0);
                    d1 = fmaf(e[j + 1], CsT[(j + 1) * KC + k], d1);
                    d2 = fmaf(e[j + 2], CsT[(j + 2) * KC + k], d2);
                    d3 = fmaf(e[j + 3], CsT[(j + 3) * KC + k], d3);
                }
                d = ((d0 + d1) + (d2 + d3)) * inv_t;
                m = fmaxf(m, d);
            }
            lg[q] = d;
        }
#pragma unroll
        for (int o = 16; o > 0; o >>= 1) m = fmaxf(m, __shfl_xor_sync(0xFFFFFFFFu, m, o));
        float s = 0.f;
#pragma unroll
        for (int q = 0; q < 4; q++) {
            int k = lane + 32 * q;
            if (k < KC) { lg[q] = __expf(lg[q] - m); s += lg[q]; }
        }
#pragma unroll
        for (int o = 16; o > 0; o >>= 1) s += __shfl_xor_sync(0xFFFFFFFFu, s, o);
        float inv_s = 1.0f / s;
        float* so = out + (size_t)NN * EMBD + (size_t)w * KC;
#pragma unroll
        for (int q = 0; q < 4; q++) {
            int k = lane + 32 * q;
            if (k < KC) so[k] = lg[q] * inv_s;
        }
    }
}

// -----------------------------------------------------------------------------
extern "C" void kernel_launch(void* const* d_in, const int* in_sizes, int n_in,
                              void* d_out, int out_size) {
    const float* x       = (const float*)d_in[0];
    const int*   ei      = (const int*)d_in[1];
    const float* W1      = (const float*)d_in[2];
    const float* b1      = (const float*)d_in[3];
    const float* gamma   = (const float*)d_in[4];
    const float* beta    = (const float*)d_in[5];
    const float* W2      = (const float*)d_in[6];
    const float* b2      = (const float*)d_in[7];
    const float* centers = (const float*)d_in[8];
    const float* temp    = (const float*)d_in[9];
    float* out = (float*)d_out;

    k_init<<<(NN + 255) / 256, 256>>>();
    k_count<<<(EE + 255) / 256, 256>>>(ei);
    k_scan1<<<NB, 1024>>>();
    k_scan2<<<1, 128>>>();
    k_scan3<<<(NN + 255) / 256, 256>>>();
    k_fill<<<(EE + 255) / 256, 256>>>(ei);
    k_gemm1<<<(NN + 127) / 128, 256>>>(x, W1);
    k_gather1<<<(NN * 32 + 255) / 256, 256>>>(b1);
    k_bnstats<<<1024, 128>>>();
    k_bn_final<<<1, 128>>>(gamma, beta);
    k_gemm2<<<(NN + 127) / 128, 256>>>(W2);
    k_gather2<<<(NN * 32 + 255) / 256, 256>>>(b2, out);
    k_logits<<<LBLK, 256>>>(centers, temp, out);
}